// round 3
// baseline (speedup 1.0000x reference)
#include <cuda_runtime.h>
#include <cuda_fp16.h>
#include <cstdint>

// ============================ problem constants ============================
namespace {
constexpr int B_SZ  = 16;
constexpr int LKDIM = 8192;
constexpr int DDIM  = 1024;
constexpr int HDIM  = 1024;
constexpr int BL    = B_SZ * LKDIM;          // 131072 GEMM rows

constexpr int M_TILE  = 128;
constexpr int N_TILE  = 256;                 // h-chunk per pass
constexpr int PASSES  = HDIM / N_TILE;       // 4
constexpr int K_HALF  = 64;                  // halves per K stage (128B rows)
constexpr int K_STEPS = DDIM / K_HALF;       // 16
constexpr int THREADS = 512;                 // 16 warps: 2(M) x 8(N)
constexpr int NUM_TILES = BL / M_TILE;       // 1024 CTAs

constexpr int A_BYTES = M_TILE * 128;        // 16 KB / stage
constexpr int B_BYTES = N_TILE * 128;        // 32 KB / stage

// dynamic SMEM layout
constexpr int OFF_Q   = 0;                       // 1024 f32
constexpr int OFF_WV  = OFF_Q  + HDIM * 4;       // 1024 f32
constexpr int OFF_OUT = OFF_WV + HDIM * 4;       // 128 f32
constexpr int OFF_A   = 9216;                    // 1024-aligned
constexpr int OFF_B   = OFF_A + 2 * A_BYTES;     // 41984
constexpr int SMEM_TOTAL = OFF_B + 2 * B_BYTES;  // 107520 B
} // namespace

// ============================ device scratch ==============================
__device__ float  g_q [B_SZ * HDIM];   // projected queries (fp32, exact)
__device__ __half g_wt[HDIM * DDIM];   // W_k^T: [h][d] fp16

// ============================ helpers =====================================
__device__ __forceinline__ uint32_t smem_u32(const void* p) {
    uint32_t a;
    asm("{ .reg .u64 t; cvta.to.shared.u64 t, %1; cvt.u32.u64 %0, t; }"
        : "=r"(a) : "l"(p));
    return a;
}
__device__ __forceinline__ uint32_t swz128(uint32_t off) {
    return off ^ ((off >> 3) & 0x70);
}
__device__ __forceinline__ void ldm_x4(uint32_t& r0, uint32_t& r1,
                                       uint32_t& r2, uint32_t& r3, uint32_t addr) {
    asm volatile("ldmatrix.sync.aligned.m8n8.x4.shared.b16 {%0,%1,%2,%3}, [%4];"
                 : "=r"(r0), "=r"(r1), "=r"(r2), "=r"(r3) : "r"(addr));
}
__device__ __forceinline__ void mma16816(float* c, const uint32_t* a, const uint32_t* b) {
    asm volatile(
        "mma.sync.aligned.m16n8k16.row.col.f32.f16.f16.f32 "
        "{%0,%1,%2,%3}, {%4,%5,%6,%7}, {%8,%9}, {%0,%1,%2,%3};"
        : "+f"(c[0]), "+f"(c[1]), "+f"(c[2]), "+f"(c[3])
        : "r"(a[0]), "r"(a[1]), "r"(a[2]), "r"(a[3]), "r"(b[0]), "r"(b[1]));
}
__device__ __forceinline__ void cp_async16(uint32_t saddr, const void* gaddr) {
    asm volatile("cp.async.cg.shared.global [%0], [%1], 16;"
                 :: "r"(saddr), "l"(gaddr) : "memory");
}
#define CP_COMMIT() asm volatile("cp.async.commit_group;" ::: "memory")
#define CP_WAIT0()  asm volatile("cp.async.wait_group 0;"  ::: "memory")

__device__ __forceinline__ float fast_tanh(float x) {
    float r;
    asm("tanh.approx.f32 %0, %1;" : "=f"(r) : "f"(x));
    return r;
}

// ============================ prep kernels ================================
__global__ void qproj_kernel(const float* __restrict__ queries,
                             const float* __restrict__ W_q) {
    __shared__ float sq[DDIM];
    int b = blockIdx.x;
    for (int i = threadIdx.x; i < DDIM; i += 256) sq[i] = queries[b * DDIM + i];
    __syncthreads();
    int h = threadIdx.x;
    float a0 = 0.f, a1 = 0.f, a2 = 0.f, a3 = 0.f;
    for (int d = 0; d < DDIM; d++) {
        float qd = sq[d];
        const float* w = W_q + (size_t)d * HDIM;
        a0 = fmaf(qd, w[h],       a0);
        a1 = fmaf(qd, w[h + 256], a1);
        a2 = fmaf(qd, w[h + 512], a2);
        a3 = fmaf(qd, w[h + 768], a3);
    }
    g_q[b * HDIM + h]       = a0;
    g_q[b * HDIM + h + 256] = a1;
    g_q[b * HDIM + h + 512] = a2;
    g_q[b * HDIM + h + 768] = a3;
}

__global__ void wconv_kernel(const float* __restrict__ W_k) {
    int idx = blockIdx.x * 256 + threadIdx.x;   // over D*H
    int d = idx >> 10, h = idx & 1023;
    g_wt[(size_t)h * DDIM + d] = __float2half_rn(W_k[idx]);
}

// ============================ main fused kernel ===========================
__global__ void __launch_bounds__(THREADS, 1)
attn_main_kernel(const float* __restrict__ keys,
                 const float* __restrict__ w_v,
                 float* __restrict__ out) {
    extern __shared__ char smem[];
    const uint32_t sb  = smem_u32(smem);
    const int tid  = threadIdx.x;
    const int wid  = tid >> 5;
    const int lane = tid & 31;
    const int warp_m = wid >> 3;     // 0..1
    const int warp_n = wid & 7;      // 0..7
    const int row0 = blockIdx.x * M_TILE;
    const int b    = row0 >> 13;     // 8192 rows per batch

    float* s_q   = reinterpret_cast<float*>(smem + OFF_Q);
    float* s_wv  = reinterpret_cast<float*>(smem + OFF_WV);
    float* s_out = reinterpret_cast<float*>(smem + OFF_OUT);

    for (int i = tid; i < HDIM; i += THREADS) {
        s_q[i]  = g_q[b * HDIM + i];
        s_wv[i] = w_v[i];
    }
    if (tid < M_TILE) s_out[tid] = 0.f;

    // lane-invariant ldmatrix address pieces
    const int rowA  = warp_m * 64 + (lane & 15);
    const int colA8 = (lane >> 4) << 3;                       // 0 or 8 halves
    const int gB    = lane >> 3;
    const int rowB  = warp_n * 32 + (lane & 7) + ((gB >> 1) << 3);
    const int colB8 = (gB & 1) << 3;

    // A-loader indices: 4 x float4 per thread per stage
    const int amRow [4] = { (tid + 0*THREADS) >> 4, (tid + 1*THREADS) >> 4,
                            (tid + 2*THREADS) >> 4, (tid + 3*THREADS) >> 4 };
    const int amQ   [4] = { tid & 15, tid & 15, tid & 15, tid & 15 };

    float sc[8];
#pragma unroll
    for (int i = 0; i < 8; i++) sc[i] = 0.f;

    __syncthreads();   // publish s_q / s_wv / s_out zero

    for (int nc = 0; nc < PASSES; nc++) {
        const int n0 = nc * N_TILE;
        float acc[4][4][4];
#pragma unroll
        for (int mi = 0; mi < 4; mi++)
#pragma unroll
            for (int nf = 0; nf < 4; nf++)
#pragma unroll
                for (int c = 0; c < 4; c++) acc[mi][nf][c] = 0.f;

        // ---- prologue: stage 0 ----
        {
            float4 ar[4];
#pragma unroll
            for (int i = 0; i < 4; i++)
                ar[i] = *reinterpret_cast<const float4*>(
                    keys + (size_t)(row0 + amRow[i]) * DDIM + 0 + amQ[i] * 4);
#pragma unroll
            for (int i = 0; i < 4; i++) {   // B stage 0: 4 x 16B per thread
                int idx = tid + i * THREADS;            // 0..2047
                int h = idx >> 3, c = idx & 7;
                cp_async16(sb + OFF_B + swz128((uint32_t)(h * 128 + c * 16)),
                           g_wt + (size_t)(n0 + h) * DDIM + 0 + c * 8);
            }
            CP_COMMIT();
#pragma unroll
            for (int i = 0; i < 4; i++) {
                union { __half2 h[2]; uint2 u; } cv;
                cv.h[0] = __floats2half2_rn(ar[i].x, ar[i].y);
                cv.h[1] = __floats2half2_rn(ar[i].z, ar[i].w);
                *reinterpret_cast<uint2*>(smem + OFF_A +
                    swz128((uint32_t)(amRow[i] * 128 + amQ[i] * 8))) = cv.u;
            }
            CP_WAIT0();
            __syncthreads();
        }

        for (int ks = 0; ks < K_STEPS; ks++) {
            const int cur = ks & 1;
            const bool has_next = (ks + 1 < K_STEPS);
            float4 ar[4];
            if (has_next) {
                const int k0 = (ks + 1) * K_HALF;
#pragma unroll
                for (int i = 0; i < 4; i++)
                    ar[i] = *reinterpret_cast<const float4*>(
                        keys + (size_t)(row0 + amRow[i]) * DDIM + k0 + amQ[i] * 4);
#pragma unroll
                for (int i = 0; i < 4; i++) {
                    int idx = tid + i * THREADS;
                    int h = idx >> 3, c = idx & 7;
                    cp_async16(sb + OFF_B + (cur ^ 1) * B_BYTES +
                                   swz128((uint32_t)(h * 128 + c * 16)),
                               g_wt + (size_t)(n0 + h) * DDIM + k0 + c * 8);
                }
                CP_COMMIT();
            }

            // ---- compute current stage ----
            {
                const uint32_t abase = sb + OFF_A + cur * A_BYTES;
                const uint32_t bbase = sb + OFF_B + cur * B_BYTES;
#pragma unroll
                for (int kf = 0; kf < 4; kf++) {
                    const int k0 = kf * 16;
                    uint32_t a[4][4], bb[4][2];
#pragma unroll
                    for (int mi = 0; mi < 4; mi++)
                        ldm_x4(a[mi][0], a[mi][1], a[mi][2], a[mi][3],
                               abase + swz128((uint32_t)((rowA + mi * 16) * 128 +
                                                         (k0 + colA8) * 2)));
#pragma unroll
                    for (int p = 0; p < 2; p++)
                        ldm_x4(bb[2*p][0], bb[2*p][1], bb[2*p+1][0], bb[2*p+1][1],
                               bbase + swz128((uint32_t)((rowB + p * 16) * 128 +
                                                         (k0 + colB8) * 2)));
#pragma unroll
                    for (int mi = 0; mi < 4; mi++)
#pragma unroll
                        for (int nf = 0; nf < 4; nf++)
                            mma16816(acc[mi][nf], a[mi], bb[nf]);
                }
            }

            if (has_next) {
#pragma unroll
                for (int i = 0; i < 4; i++) {
                    union { __half2 h[2]; uint2 u; } cv;
                    cv.h[0] = __floats2half2_rn(ar[i].x, ar[i].y);
                    cv.h[1] = __floats2half2_rn(ar[i].z, ar[i].w);
                    *reinterpret_cast<uint2*>(smem + OFF_A + (cur ^ 1) * A_BYTES +
                        swz128((uint32_t)(amRow[i] * 128 + amQ[i] * 8))) = cv.u;
                }
            }
            CP_WAIT0();
            __syncthreads();
        }

        // ---- fused epilogue for this h-chunk ----
        const int t2 = (lane & 3) * 2;
#pragma unroll
        for (int mi = 0; mi < 4; mi++) {
#pragma unroll
            for (int nf = 0; nf < 4; nf++) {
                const int n = n0 + warp_n * 32 + nf * 8 + t2;
                const float q0 = s_q[n],  q1 = s_q[n + 1];
                const float w0 = s_wv[n], w1 = s_wv[n + 1];
                sc[mi*2]     = fmaf(fast_tanh(acc[mi][nf][0] + q0), w0, sc[mi*2]);
                sc[mi*2]     = fmaf(fast_tanh(acc[mi][nf][1] + q1), w1, sc[mi*2]);
                sc[mi*2 + 1] = fmaf(fast_tanh(acc[mi][nf][2] + q0), w0, sc[mi*2+1]);
                sc[mi*2 + 1] = fmaf(fast_tanh(acc[mi][nf][3] + q1), w1, sc[mi*2+1]);
            }
        }
    }

    // ---- reduce scores: over the 4 lanes sharing each row, then across warps
#pragma unroll
    for (int i = 0; i < 8; i++) {
        sc[i] += __shfl_xor_sync(0xFFFFFFFFu, sc[i], 1);
        sc[i] += __shfl_xor_sync(0xFFFFFFFFu, sc[i], 2);
    }
    if ((lane & 3) == 0) {
        const int g = lane >> 2;
#pragma unroll
        for (int mi = 0; mi < 4; mi++) {
            atomicAdd(&s_out[warp_m * 64 + mi * 16 + g],     sc[mi*2]);
            atomicAdd(&s_out[warp_m * 64 + mi * 16 + g + 8], sc[mi*2 + 1]);
        }
    }
    __syncthreads();
    if (tid < M_TILE) out[row0 + tid] = s_out[tid];
}

// ============================ launch ======================================
extern "C" void kernel_launch(void* const* d_in, const int* in_sizes, int n_in,
                              void* d_out, int out_size) {
    const float* queries = (const float*)d_in[0];
    const float* keys    = (const float*)d_in[1];
    const float* W_q     = (const float*)d_in[2];
    const float* W_k     = (const float*)d_in[3];
    const float* w_v     = (const float*)d_in[4];
    float* out = (float*)d_out;

    cudaFuncSetAttribute(attn_main_kernel,
                         cudaFuncAttributeMaxDynamicSharedMemorySize, SMEM_TOTAL);

    qproj_kernel<<<B_SZ, 256>>>(queries, W_q);
    wconv_kernel<<<(HDIM * DDIM) / 256, 256>>>(W_k);
    attn_main_kernel<<<NUM_TILES, THREADS, SMEM_TOTAL>>>(keys, w_v, out);
}

// round 4
// speedup vs baseline: 1.1133x; 1.1133x over previous
#include <cuda_runtime.h>
#include <cuda_fp16.h>
#include <cstdint>

// ============================ problem constants ============================
namespace {
constexpr int B_SZ  = 16;
constexpr int LKDIM = 8192;
constexpr int DDIM  = 1024;
constexpr int HDIM  = 1024;
constexpr int BL    = B_SZ * LKDIM;          // 131072 GEMM rows

constexpr int M_TILE  = 128;
constexpr int N_TILE  = 256;                 // h-chunk per pass
constexpr int PASSES  = HDIM / N_TILE;       // 4
constexpr int K_HALF  = 64;                  // halves per K stage (128B rows)
constexpr int K_STEPS = DDIM / K_HALF;       // 16
constexpr int THREADS = 512;                 // 16 warps: 2(M) x 8(N)
constexpr int NUM_TILES = BL / M_TILE;       // 1024 CTAs

constexpr int A_BYTES = M_TILE * 128;        // 16 KB / stage
constexpr int B_BYTES = N_TILE * 128;        // 32 KB / stage

// dynamic SMEM layout
constexpr int OFF_Q   = 0;                       // 1024 f32
constexpr int OFF_WV  = OFF_Q  + HDIM * 4;       // 1024 f32
constexpr int OFF_OUT = OFF_WV + HDIM * 4;       // 128*4 f32 partial slots
constexpr int OFF_A   = 10240;                   // 1024-aligned
constexpr int OFF_B   = OFF_A + 2 * A_BYTES;     // +32KB
constexpr int SMEM_TOTAL = OFF_B + 2 * B_BYTES;  // 108544 B

// prep kernel split
constexpr int WCONV_BLOCKS = (HDIM * DDIM) / 256;   // 4096
constexpr int QPROJ_BLOCKS = B_SZ * 4;              // 64 (16 b x 4 h-chunks)
} // namespace

// ============================ device scratch ==============================
__device__ float  g_q [B_SZ * HDIM];   // projected queries (fp32, exact)
__device__ __half g_wt[HDIM * DDIM];   // W_k^T: [h][d] fp16

// ============================ helpers =====================================
__device__ __forceinline__ uint32_t smem_u32(const void* p) {
    uint32_t a;
    asm("{ .reg .u64 t; cvta.to.shared.u64 t, %1; cvt.u32.u64 %0, t; }"
        : "=r"(a) : "l"(p));
    return a;
}
__device__ __forceinline__ uint32_t swz128(uint32_t off) {
    return off ^ ((off >> 3) & 0x70);
}
__device__ __forceinline__ void ldm_x4(uint32_t& r0, uint32_t& r1,
                                       uint32_t& r2, uint32_t& r3, uint32_t addr) {
    asm volatile("ldmatrix.sync.aligned.m8n8.x4.shared.b16 {%0,%1,%2,%3}, [%4];"
                 : "=r"(r0), "=r"(r1), "=r"(r2), "=r"(r3) : "r"(addr));
}
__device__ __forceinline__ void mma16816(float* c, const uint32_t* a, const uint32_t* b) {
    asm volatile(
        "mma.sync.aligned.m16n8k16.row.col.f32.f16.f16.f32 "
        "{%0,%1,%2,%3}, {%4,%5,%6,%7}, {%8,%9}, {%0,%1,%2,%3};"
        : "+f"(c[0]), "+f"(c[1]), "+f"(c[2]), "+f"(c[3])
        : "r"(a[0]), "r"(a[1]), "r"(a[2]), "r"(a[3]), "r"(b[0]), "r"(b[1]));
}
__device__ __forceinline__ void cp_async16(uint32_t saddr, const void* gaddr) {
    asm volatile("cp.async.cg.shared.global [%0], [%1], 16;"
                 :: "r"(saddr), "l"(gaddr) : "memory");
}
#define CP_COMMIT() asm volatile("cp.async.commit_group;" ::: "memory")
#define CP_WAIT0()  asm volatile("cp.async.wait_group 0;"  ::: "memory")

__device__ __forceinline__ float fast_tanh(float x) {
    float r;
    asm("tanh.approx.f32 %0, %1;" : "=f"(r) : "f"(x));
    return r;
}

// ============================ prep kernel (merged) =========================
// blocks [0, WCONV_BLOCKS)              : W_k -> g_wt (transpose + fp16)
// blocks [WCONV_BLOCKS, +QPROJ_BLOCKS)  : q = queries @ W_q  (fp32 exact)
__global__ void prep_kernel(const float* __restrict__ W_k,
                            const float* __restrict__ queries,
                            const float* __restrict__ W_q) {
    if (blockIdx.x < WCONV_BLOCKS) {
        int idx = blockIdx.x * 256 + threadIdx.x;   // over D*H
        int d = idx >> 10, h = idx & 1023;
        g_wt[(size_t)h * DDIM + d] = __float2half_rn(W_k[idx]);
    } else {
        const int qb = blockIdx.x - WCONV_BLOCKS;   // 0..63
        const int b  = qb >> 2;                     // batch
        const int h0 = (qb & 3) * 256;              // h-chunk base
        __shared__ float sq[DDIM];
        for (int i = threadIdx.x; i < DDIM; i += 256)
            sq[i] = queries[b * DDIM + i];
        __syncthreads();
        const int h = h0 + threadIdx.x;
        float acc = 0.f;
        const float* w = W_q + h;
#pragma unroll 8
        for (int d = 0; d < DDIM; d++)
            acc = fmaf(sq[d], w[(size_t)d * HDIM], acc);
        g_q[b * HDIM + h] = acc;
    }
}

// ============================ main fused kernel ===========================
__global__ void __launch_bounds__(THREADS, 1)
attn_main_kernel(const float* __restrict__ keys,
                 const float* __restrict__ w_v,
                 float* __restrict__ out) {
    extern __shared__ char smem[];
    const uint32_t sb  = smem_u32(smem);
    const int tid  = threadIdx.x;
    const int wid  = tid >> 5;
    const int lane = tid & 31;
    const int warp_m = wid >> 3;     // 0..1
    const int warp_n = wid & 7;      // 0..7
    const int row0 = blockIdx.x * M_TILE;
    const int b    = row0 >> 13;     // 8192 rows per batch

    float* s_q   = reinterpret_cast<float*>(smem + OFF_Q);
    float* s_wv  = reinterpret_cast<float*>(smem + OFF_WV);
    float* s_out = reinterpret_cast<float*>(smem + OFF_OUT);  // [4 groups][128 rows]

    for (int i = tid; i < HDIM; i += THREADS) {
        s_q[i]  = g_q[b * HDIM + i];
        s_wv[i] = w_v[i];
    }

    // lane-invariant ldmatrix address pieces
    const int rowA  = warp_m * 64 + (lane & 15);
    const int colA8 = (lane >> 4) << 3;                       // 0 or 8 halves
    const int gB    = lane >> 3;
    const int rowB  = warp_n * 32 + (lane & 7) + ((gB >> 1) << 3);
    const int colB8 = (gB & 1) << 3;

    // A-loader indices: 4 x float4 per thread per stage
    const int amRow [4] = { (tid + 0*THREADS) >> 4, (tid + 1*THREADS) >> 4,
                            (tid + 2*THREADS) >> 4, (tid + 3*THREADS) >> 4 };
    const int amQ = tid & 15;

    float sc[8];
#pragma unroll
    for (int i = 0; i < 8; i++) sc[i] = 0.f;

    __syncthreads();   // publish s_q / s_wv

    for (int nc = 0; nc < PASSES; nc++) {
        const int n0 = nc * N_TILE;
        float acc[4][4][4];
#pragma unroll
        for (int mi = 0; mi < 4; mi++)
#pragma unroll
            for (int nf = 0; nf < 4; nf++)
#pragma unroll
                for (int c = 0; c < 4; c++) acc[mi][nf][c] = 0.f;

        // ---- prologue: stage 0 ----
        {
            float4 ar[4];
#pragma unroll
            for (int i = 0; i < 4; i++)
                ar[i] = *reinterpret_cast<const float4*>(
                    keys + (size_t)(row0 + amRow[i]) * DDIM + 0 + amQ * 4);
#pragma unroll
            for (int i = 0; i < 4; i++) {   // B stage 0: 4 x 16B per thread
                int idx = tid + i * THREADS;            // 0..2047
                int h = idx >> 3, c = idx & 7;
                cp_async16(sb + OFF_B + swz128((uint32_t)(h * 128 + c * 16)),
                           g_wt + (size_t)(n0 + h) * DDIM + 0 + c * 8);
            }
            CP_COMMIT();
#pragma unroll
            for (int i = 0; i < 4; i++) {
                union { __half2 h[2]; uint2 u; } cv;
                cv.h[0] = __floats2half2_rn(ar[i].x, ar[i].y);
                cv.h[1] = __floats2half2_rn(ar[i].z, ar[i].w);
                *reinterpret_cast<uint2*>(smem + OFF_A +
                    swz128((uint32_t)(amRow[i] * 128 + amQ * 8))) = cv.u;
            }
            CP_WAIT0();
            __syncthreads();
        }

        for (int ks = 0; ks < K_STEPS; ks++) {
            const int cur = ks & 1;
            const bool has_next = (ks + 1 < K_STEPS);
            float4 ar[4];
            if (has_next) {
                const int k0 = (ks + 1) * K_HALF;
#pragma unroll
                for (int i = 0; i < 4; i++)
                    ar[i] = *reinterpret_cast<const float4*>(
                        keys + (size_t)(row0 + amRow[i]) * DDIM + k0 + amQ * 4);
#pragma unroll
                for (int i = 0; i < 4; i++) {
                    int idx = tid + i * THREADS;
                    int h = idx >> 3, c = idx & 7;
                    cp_async16(sb + OFF_B + (cur ^ 1) * B_BYTES +
                                   swz128((uint32_t)(h * 128 + c * 16)),
                               g_wt + (size_t)(n0 + h) * DDIM + k0 + c * 8);
                }
                CP_COMMIT();
            }

            // ---- compute current stage ----
            {
                const uint32_t abase = sb + OFF_A + cur * A_BYTES;
                const uint32_t bbase = sb + OFF_B + cur * B_BYTES;
#pragma unroll
                for (int kf = 0; kf < 4; kf++) {
                    const int k0 = kf * 16;
                    uint32_t a[4][4], bb[4][2];
#pragma unroll
                    for (int mi = 0; mi < 4; mi++)
                        ldm_x4(a[mi][0], a[mi][1], a[mi][2], a[mi][3],
                               abase + swz128((uint32_t)((rowA + mi * 16) * 128 +
                                                         (k0 + colA8) * 2)));
#pragma unroll
                    for (int p = 0; p < 2; p++)
                        ldm_x4(bb[2*p][0], bb[2*p][1], bb[2*p+1][0], bb[2*p+1][1],
                               bbase + swz128((uint32_t)((rowB + p * 16) * 128 +
                                                         (k0 + colB8) * 2)));
#pragma unroll
                    for (int mi = 0; mi < 4; mi++)
#pragma unroll
                        for (int nf = 0; nf < 4; nf++)
                            mma16816(acc[mi][nf], a[mi], bb[nf]);
                }
            }

            if (has_next) {
#pragma unroll
                for (int i = 0; i < 4; i++) {
                    union { __half2 h[2]; uint2 u; } cv;
                    cv.h[0] = __floats2half2_rn(ar[i].x, ar[i].y);
                    cv.h[1] = __floats2half2_rn(ar[i].z, ar[i].w);
                    *reinterpret_cast<uint2*>(smem + OFF_A + (cur ^ 1) * A_BYTES +
                        swz128((uint32_t)(amRow[i] * 128 + amQ * 8))) = cv.u;
                }
            }
            CP_WAIT0();
            __syncthreads();
        }

        // ---- fused epilogue for this h-chunk ----
        const int t2 = (lane & 3) * 2;
#pragma unroll
        for (int mi = 0; mi < 4; mi++) {
#pragma unroll
            for (int nf = 0; nf < 4; nf++) {
                const int n = n0 + warp_n * 32 + nf * 8 + t2;
                const float q0 = s_q[n],  q1 = s_q[n + 1];
                const float w0 = s_wv[n], w1 = s_wv[n + 1];
                sc[mi*2]     = fmaf(fast_tanh(acc[mi][nf][0] + q0), w0, sc[mi*2]);
                sc[mi*2]     = fmaf(fast_tanh(acc[mi][nf][1] + q1), w1, sc[mi*2]);
                sc[mi*2 + 1] = fmaf(fast_tanh(acc[mi][nf][2] + q0), w0, sc[mi*2+1]);
                sc[mi*2 + 1] = fmaf(fast_tanh(acc[mi][nf][3] + q1), w1, sc[mi*2+1]);
            }
        }
    }

    // ---- reduce scores ----
    // lanes sharing a row (quad-pairs) first, then 8 N-warps via SMEM slots.
#pragma unroll
    for (int i = 0; i < 8; i++) {
        sc[i] += __shfl_xor_sync(0xFFFFFFFFu, sc[i], 1);
        sc[i] += __shfl_xor_sync(0xFFFFFFFFu, sc[i], 2);
    }
    __syncthreads();   // s_out reuse safe (after last epilogue reads of s_q)
    // warp_n pairs write disjoint group slots: group = warp_n >> 1
    // within a pair, the two warps touch the same slot -> split by parity
    if ((lane & 3) == 0) {
        const int g = lane >> 2;                  // 0..7
        const int grp = warp_n >> 1;              // 0..3
        const int par = warp_n & 1;               // 0 or 1
        float* slot = s_out + grp * M_TILE;
#pragma unroll
        for (int mi = 0; mi < 4; mi++) {
            const int r0 = warp_m * 64 + mi * 16 + g;
            if (par == 0) {
                slot[r0]     = sc[mi*2];
                slot[r0 + 8] = sc[mi*2 + 1];
            }
        }
        __syncwarp(0x11111111u);
    }
    __syncthreads();
    if ((lane & 3) == 0 && (warp_n & 1) == 1) {
        const int g = lane >> 2;
        const int grp = warp_n >> 1;
        float* slot = s_out + grp * M_TILE;
#pragma unroll
        for (int mi = 0; mi < 4; mi++) {
            const int r0 = warp_m * 64 + mi * 16 + g;
            slot[r0]     += sc[mi*2];
            slot[r0 + 8] += sc[mi*2 + 1];
        }
    }
    __syncthreads();
    if (tid < M_TILE) {
        float v = s_out[tid] + s_out[M_TILE + tid] +
                  s_out[2 * M_TILE + tid] + s_out[3 * M_TILE + tid];
        out[row0 + tid] = v;
    }
}

// ============================ launch ======================================
extern "C" void kernel_launch(void* const* d_in, const int* in_sizes, int n_in,
                              void* d_out, int out_size) {
    const float* queries = (const float*)d_in[0];
    const float* keys    = (const float*)d_in[1];
    const float* W_q     = (const float*)d_in[2];
    const float* W_k     = (const float*)d_in[3];
    const float* w_v     = (const float*)d_in[4];
    float* out = (float*)d_out;

    cudaFuncSetAttribute(attn_main_kernel,
                         cudaFuncAttributeMaxDynamicSharedMemorySize, SMEM_TOTAL);

    prep_kernel<<<WCONV_BLOCKS + QPROJ_BLOCKS, 256>>>(W_k, queries, W_q);
    attn_main_kernel<<<NUM_TILES, THREADS, SMEM_TOTAL>>>(keys, w_v, out);
}